// round 14
// baseline (speedup 1.0000x reference)
#include <cuda_runtime.h>

// Shapes (fixed):
//   W: [D=1024, ML=8192] row-major, b: [D=1024]
//   out: [B=4, S=4096, D=1024] = broadcast_B( W[:, :S].T + b )
#define B_DIM 4
#define S_DIM 4096
#define D_DIM 1024
#define ML_DIM 8192

#define TROW 33  // stride 33: STS bank=(4s4+k+drow)%32, LDS bank=(sl+4dg+j)%32 -> conflict-free

// Final form: v10 topology (64s x 32d per 256-thread CTA, s-major grid,
// 2048 CTAs -- best bench at 14.784us) + 32-bit store indexing.
// Load : 2 independent LDG.128 staged up front, 8 conflict-free scalar STS,
//        ONE barrier.
// Store: per subtile, 4 conflict-free scalar LDS + bias -> float4 ->
//        4 coalesced streaming STG.128 (one per batch copy).
__global__ void __launch_bounds__(256)
posemb_v14(const float4* __restrict__ W4,
           const float4* __restrict__ bias4,
           float4* __restrict__ out4) {
    __shared__ float tile[2][32 * TROW];

    const int t  = threadIdx.x;
    const int s0 = blockIdx.x * 64;   // s-major rasterization (v10, best bench)
    const int d0 = blockIdx.y * 32;

    const int drow = t >> 3;   // 0..31 (d within tile)
    const int s4   = t & 7;    // 0..7  (float4 index along s, within subtile)
    const int dg   = t & 7;    // 0..7  (float4 group along d, store phase)
    const int sl   = t >> 3;   // 0..31 (s within subtile, store phase)

    const float4 bb = __ldg(&bias4[(d0 >> 2) + dg]);

    // Two independent loads staged up front (s-subtiles 0 and 1).
    const size_t rowbase = (size_t)(d0 + drow) * (ML_DIM / 4) + (s0 >> 2) + s4;
    const float4 w0 = __ldcs(&W4[rowbase]);
    const float4 w1 = __ldcs(&W4[rowbase + 8]);

    const int sb = 4 * s4;
    tile[0][(sb + 0) * TROW + drow] = w0.x;
    tile[0][(sb + 1) * TROW + drow] = w0.y;
    tile[0][(sb + 2) * TROW + drow] = w0.z;
    tile[0][(sb + 3) * TROW + drow] = w0.w;
    tile[1][(sb + 0) * TROW + drow] = w1.x;
    tile[1][(sb + 1) * TROW + drow] = w1.y;
    tile[1][(sb + 2) * TROW + drow] = w1.z;
    tile[1][(sb + 3) * TROW + drow] = w1.w;

    __syncthreads();

    // 32-bit output indexing (out = 4M float4 per batch, fits unsigned).
    const unsigned batch_stride = (unsigned)S_DIM * (D_DIM / 4);
    const unsigned base0 =
        (unsigned)(s0 + sl) * (D_DIM / 4) + (unsigned)(d0 >> 2) + dg;

#pragma unroll
    for (int u = 0; u < 2; u++) {
        const float* row = &tile[u][sl * TROW + 4 * dg];
        float4 v;
        v.x = row[0] + bb.x;
        v.y = row[1] + bb.y;
        v.z = row[2] + bb.z;
        v.w = row[3] + bb.w;

        float4* p = out4 + (base0 + (unsigned)u * (32u * (D_DIM / 4)));
        __stcs(p,                     v);
        __stcs(p + batch_stride,      v);
        __stcs(p + 2u * batch_stride, v);
        __stcs(p + 3u * batch_stride, v);
    }
}

extern "C" void kernel_launch(void* const* d_in, const int* in_sizes, int n_in,
                              void* d_out, int out_size) {
    (void)in_sizes; (void)n_in; (void)out_size;
    const float4* W4    = (const float4*)d_in[1];
    const float4* bias4 = (const float4*)d_in[2];
    float4* out4        = (float4*)d_out;

    dim3 block(256);
    dim3 grid(S_DIM / 64, D_DIM / 32);  // 64 x 32 = 2048 CTAs, s-major order
    posemb_v14<<<grid, block>>>(W4, bias4, out4);
}

// round 15
// speedup vs baseline: 1.0420x; 1.0420x over previous
#include <cuda_runtime.h>

// Shapes (fixed):
//   W: [D=1024, ML=8192] row-major, b: [D=1024]
//   out: [B=4, S=4096, D=1024] = broadcast_B( W[:, :S].T + b )
#define B_DIM 4
#define S_DIM 4096
#define D_DIM 1024
#define ML_DIM 8192

#define TROW 33  // stride 33: STS bank=(4s4+k+drow)%32, LDS bank=(sl+4dg+j)%32 -> conflict-free

// FINAL: 64s x 32d tile per 256-thread CTA (2048 CTAs, s-major grid).
// Empirically best bench (14.784us); ncu steady state at the LTS
// write-service floor (~13.6-13.9us) shared by all good variants.
// Load : 2 independent LDG.128 staged up front (MLP=2), then
//        8 conflict-free scalar STS, ONE barrier.
// Store: per subtile, 4 conflict-free scalar LDS + bias -> float4 ->
//        4 coalesced streaming STG.128 (one per batch copy).
__global__ void __launch_bounds__(256)
posemb_final(const float4* __restrict__ W4,
             const float4* __restrict__ bias4,
             float4* __restrict__ out4) {
    __shared__ float tile[2][32 * TROW];

    const int t  = threadIdx.x;
    const int s0 = blockIdx.x * 64;
    const int d0 = blockIdx.y * 32;

    const int drow = t >> 3;   // 0..31 (d within tile)
    const int s4   = t & 7;    // 0..7  (float4 index along s, within subtile)
    const int dg   = t & 7;    // 0..7  (float4 group along d, store phase)
    const int sl   = t >> 3;   // 0..31 (s within subtile, store phase)

    const float4 bb = __ldg(&bias4[(d0 >> 2) + dg]);

    // Two independent loads: covers s-subtile 0 (s0..s0+31) and 1 (s0+32..+63).
    const size_t rowbase = (size_t)(d0 + drow) * (ML_DIM / 4) + (s0 >> 2) + s4;
    const float4 w0 = __ldcs(&W4[rowbase]);
    const float4 w1 = __ldcs(&W4[rowbase + 8]);

    const int sb = 4 * s4;
    tile[0][(sb + 0) * TROW + drow] = w0.x;
    tile[0][(sb + 1) * TROW + drow] = w0.y;
    tile[0][(sb + 2) * TROW + drow] = w0.z;
    tile[0][(sb + 3) * TROW + drow] = w0.w;
    tile[1][(sb + 0) * TROW + drow] = w1.x;
    tile[1][(sb + 1) * TROW + drow] = w1.y;
    tile[1][(sb + 2) * TROW + drow] = w1.z;
    tile[1][(sb + 3) * TROW + drow] = w1.w;

    __syncthreads();

    const size_t batch_stride = (size_t)S_DIM * (D_DIM / 4);

#pragma unroll
    for (int u = 0; u < 2; u++) {
        const float* row = &tile[u][sl * TROW + 4 * dg];
        float4 v;
        v.x = row[0] + bb.x;
        v.y = row[1] + bb.y;
        v.z = row[2] + bb.z;
        v.w = row[3] + bb.w;

        float4* p = out4 + (size_t)(s0 + 32 * u + sl) * (D_DIM / 4) + (d0 >> 2) + dg;
        __stcs(p,                    v);
        __stcs(p + batch_stride,     v);
        __stcs(p + 2 * batch_stride, v);
        __stcs(p + 3 * batch_stride, v);
    }
}

extern "C" void kernel_launch(void* const* d_in, const int* in_sizes, int n_in,
                              void* d_out, int out_size) {
    (void)in_sizes; (void)n_in; (void)out_size;
    const float4* W4    = (const float4*)d_in[1];
    const float4* bias4 = (const float4*)d_in[2];
    float4* out4        = (float4*)d_out;

    dim3 block(256);
    dim3 grid(S_DIM / 64, D_DIM / 32);  // 64 x 32 = 2048 CTAs, s-major order
    posemb_final<<<grid, block>>>(W4, bias4, out4);
}